// round 15
// baseline (speedup 1.0000x reference)
#include <cuda_runtime.h>
#include <cuda_bf16.h>
#include <cstdint>

#define D1 256
#define D2 128
#define K_DIM 256
#define ROWB 80
#define MPAD 100096

static const int MAX_N = 100000;
static const int MAX_E = 1600000;

__device__ __nv_bfloat16 g_y1[MAX_N * D1];
__device__ float g_z1[MAX_N * D1];
__device__ __nv_bfloat16 g_y2[MAX_N * D2];
__device__ float g_z2[MAX_N * D2];
__device__ float g_deg[MAX_N];
__device__ uint8_t g_xhi[8ull * MPAD * ROWB];
__device__ uint8_t g_xlo[8ull * MPAD * ROWB];
__device__ uint8_t g_hhi[8ull * MPAD * ROWB];
__device__ uint8_t g_hlo[8ull * MPAD * ROWB];
__device__ uint8_t g_w1hi[8 * 512 * ROWB];
__device__ uint8_t g_w1lo[8 * 512 * ROWB];
__device__ uint8_t g_w2hi[8 * 256 * ROWB];
__device__ uint8_t g_w2lo[8 * 256 * ROWB];
__device__ int g_rowptr[MAX_N];
__device__ int g_cursor[MAX_N];
__device__ int g_csr[MAX_E];
__device__ int g_bsum[128];
__device__ int g_boff[128];

#define SCAN_BLK 1024

__device__ __forceinline__ uint32_t smem_to_u32(const void* p) {
    uint32_t a;
    asm("{ .reg .u64 t; cvta.to.shared.u64 t, %1; cvt.u32.u64 %0, t; }" : "=r"(a) : "l"(p));
    return a;
}
__device__ __forceinline__ void mma_bf16(float* c, const uint32_t* a, const uint32_t* b) {
    asm volatile("mma.sync.aligned.m16n8k16.row.col.f32.bf16.bf16.f32 "
                 "{%0,%1,%2,%3}, {%4,%5,%6,%7}, {%8,%9}, {%0,%1,%2,%3};"
                 : "+f"(c[0]), "+f"(c[1]), "+f"(c[2]), "+f"(c[3])
                 : "r"(a[0]), "r"(a[1]), "r"(a[2]), "r"(a[3]), "r"(b[0]), "r"(b[1]));
}
#define LDSM_X4(r, addr) \
    asm volatile("ldmatrix.sync.aligned.m8n8.x4.shared.b16 {%0,%1,%2,%3}, [%4];" \
                 : "=r"((r)[0]), "=r"((r)[1]), "=r"((r)[2]), "=r"((r)[3]) : "r"(addr))
#define MBAR_INIT(a, c) \
    asm volatile("mbarrier.init.shared.b64 [%0], %1;" :: "r"((uint32_t)(a)), "r"((uint32_t)(c)) : "memory")
#define MBAR_TX(a, b) \
    asm volatile("mbarrier.arrive.expect_tx.shared.b64 _, [%0], %1;" :: "r"((uint32_t)(a)), "r"((uint32_t)(b)) : "memory")
#define MBAR_WAIT(a, ph) do { \
    uint32_t _m = (uint32_t)(a), _p = (uint32_t)(ph), _d; \
    asm volatile("{\n\t.reg .pred p;\n\t" \
        "mbarrier.try_wait.parity.acquire.cta.shared::cta.b64 p, [%1], %2;\n\t" \
        "selp.b32 %0, 1, 0, p;\n\t}" : "=r"(_d) : "r"(_m), "r"(_p) : "memory"); \
    if (!_d) { \
        asm volatile("{\n\t.reg .pred P1;\n\t" \
            "WL_%=:\n\t" \
            "mbarrier.try_wait.parity.acquire.cta.shared::cta.b64 P1, [%0], %1, 0x989680;\n\t" \
            "@P1 bra.uni WD_%=;\n\t bra.uni WL_%=;\n\t WD_%=:\n\t}" \
            :: "r"(_m), "r"(_p) : "memory"); \
    } \
} while (0)
__device__ __forceinline__ void tma_bulk(uint32_t dst, const void* src, uint32_t bytes, uint32_t mbar) {
    asm volatile("cp.async.bulk.shared::cluster.global.mbarrier::complete_tx::bytes [%0], [%1], %2, [%3];"
                 :: "r"(dst), "l"(src), "r"(bytes), "r"(mbar) : "memory");
}

// ---------------------------------------------------------------------------
#define AHI_O 0
#define ALO_O (128 * ROWB)
#define BHI_O (256 * ROWB)
#define BLO_O (512 * ROWB)
#define STG (768 * ROWB)
#define MB_O (3 * STG)
#define GEMM_SMEM (3 * STG + 64)

__global__ __launch_bounds__(512, 1)
void gemm3(const uint8_t* __restrict__ Ahi, const uint8_t* __restrict__ Alo,
           const uint8_t* __restrict__ Whi, const uint8_t* __restrict__ Wlo,
           int WR, int ncb, int NSPLIT,
           __nv_bfloat16* __restrict__ outY, int ldY,
           float* __restrict__ outZ, int ldZ, const float* __restrict__ biasZ, int M) {
    extern __shared__ char smem[];
    const uint32_t sb = smem_to_u32(smem);
    const uint32_t mb = sb + MB_O;
    const int tid = threadIdx.x, wid = tid >> 5, lane = tid & 31;
    const int wr = wid >> 2, wc = wid & 3;
    const int m0 = ((int)blockIdx.x / ncb) * 128;
    const int n0 = ((int)blockIdx.x % ncb) * 256;

    float acc[2][8][4];
#pragma unroll
    for (int i = 0; i < 2; i++)
#pragma unroll
        for (int j = 0; j < 8; j++)
#pragma unroll
            for (int k = 0; k < 4; k++) acc[i][j][k] = 0.0f;

    if (tid == 0) { MBAR_INIT(mb, 1); MBAR_INIT(mb + 8, 1); MBAR_INIT(mb + 16, 1); }
    __syncthreads();

    auto issue = [&](int c, int st) {
        uint32_t m = mb + st * 8;
        uint32_t s0 = sb + (uint32_t)st * STG;
        MBAR_TX(m, STG);
        tma_bulk(s0 + AHI_O, Ahi + ((size_t)c * MPAD + m0) * ROWB, 128 * ROWB, m);
        tma_bulk(s0 + ALO_O, Alo + ((size_t)c * MPAD + m0) * ROWB, 128 * ROWB, m);
        tma_bulk(s0 + BHI_O, Whi + ((size_t)c * WR + n0) * ROWB, 256 * ROWB, m);
        tma_bulk(s0 + BLO_O, Wlo + ((size_t)c * WR + n0) * ROWB, 256 * ROWB, m);
    };
    if (tid == 0) { issue(0, 0); issue(1, 1); }

    for (int c = 0; c < 8; c++) {
        MBAR_WAIT(mb + (c % 3) * 8, (c / 3) & 1);
        __syncthreads();
        if (tid == 0 && c + 2 < 8) issue(c + 2, (c + 2) % 3);

        const uint32_t s0 = sb + (uint32_t)(c % 3) * STG;
#pragma unroll
        for (int s = 0; s < 2; s++) {
            const uint32_t ao = s0 + (uint32_t)(wr * 32 + (lane & 15)) * ROWB + ((lane >> 4) << 4) + s * 32;
            const uint32_t bo = s0 + BHI_O + (uint32_t)(wc * 64 + (lane & 7) + ((lane >> 4) << 3)) * ROWB
                                + (((lane >> 3) & 1) << 4) + s * 32;
            uint32_t ahi[2][4], alo[2][4], bbf[4][4];
#pragma unroll
            for (int mi = 0; mi < 2; mi++) {
                LDSM_X4(ahi[mi], ao + mi * (16 * ROWB));
                LDSM_X4(alo[mi], ao + ALO_O + mi * (16 * ROWB));
            }
#pragma unroll
            for (int p = 0; p < 4; p++) LDSM_X4(bbf[p], bo + p * (16 * ROWB));
#pragma unroll
            for (int mi = 0; mi < 2; mi++)
#pragma unroll
                for (int p = 0; p < 4; p++) {
                    mma_bf16(acc[mi][2 * p], ahi[mi], &bbf[p][0]);
                    mma_bf16(acc[mi][2 * p + 1], ahi[mi], &bbf[p][2]);
                    mma_bf16(acc[mi][2 * p], alo[mi], &bbf[p][0]);
                    mma_bf16(acc[mi][2 * p + 1], alo[mi], &bbf[p][2]);
                }
#pragma unroll
            for (int p = 0; p < 4; p++) LDSM_X4(bbf[p], bo + (BLO_O - BHI_O) + p * (16 * ROWB));
#pragma unroll
            for (int mi = 0; mi < 2; mi++)
#pragma unroll
                for (int p = 0; p < 4; p++) {
                    mma_bf16(acc[mi][2 * p], ahi[mi], &bbf[p][0]);
                    mma_bf16(acc[mi][2 * p + 1], ahi[mi], &bbf[p][2]);
                }
        }
    }

    const int gc0 = n0 + wc * 64;
    if (gc0 >= NSPLIT) {
        const int cbase = gc0 - NSPLIT;
#pragma unroll
        for (int mi = 0; mi < 2; mi++) {
            int r0 = m0 + wr * 32 + mi * 16 + (lane >> 2), r1 = r0 + 8;
#pragma unroll
            for (int ni = 0; ni < 8; ni++) {
                int col = cbase + ni * 8 + 2 * (lane & 3);
                float bx = __ldg(biasZ + col), by = __ldg(biasZ + col + 1);
                if (r0 < M)
                    *(float2*)(outZ + (size_t)r0 * ldZ + col) = make_float2(acc[mi][ni][0] + bx, acc[mi][ni][1] + by);
                if (r1 < M)
                    *(float2*)(outZ + (size_t)r1 * ldZ + col) = make_float2(acc[mi][ni][2] + bx, acc[mi][ni][3] + by);
            }
        }
    } else {
#pragma unroll
        for (int mi = 0; mi < 2; mi++) {
            int r0 = m0 + wr * 32 + mi * 16 + (lane >> 2), r1 = r0 + 8;
#pragma unroll
            for (int ni = 0; ni < 8; ni++) {
                int col = gc0 + ni * 8 + 2 * (lane & 3);
                if (r0 < M)
                    *(__nv_bfloat162*)(outY + (size_t)r0 * ldY + col) =
                        __nv_bfloat162(__float2bfloat16(acc[mi][ni][0]), __float2bfloat16(acc[mi][ni][1]));
                if (r1 < M)
                    *(__nv_bfloat162*)(outY + (size_t)r1 * ldY + col) =
                        __nv_bfloat162(__float2bfloat16(acc[mi][ni][2]), __float2bfloat16(acc[mi][ni][3]));
            }
        }
    }
}

// ---------------------------------------------------------------------------
__device__ __forceinline__ void split1(float v, __nv_bfloat16& h, __nv_bfloat16& l) {
    h = __float2bfloat16(v);
    l = __float2bfloat16(v - __bfloat162float(h));
}
__device__ __forceinline__ void store_p(uint8_t* hi, uint8_t* lo, size_t rowbase, int kq4, float4 v) {
    __nv_bfloat16 h0, h1, h2, h3, l0, l1, l2, l3;
    split1(v.x, h0, l0); split1(v.y, h1, l1);
    split1(v.z, h2, l2); split1(v.w, h3, l3);
    size_t off = rowbase + (size_t)(kq4 & 7) * 8;
    *(__nv_bfloat162*)(hi + off) = __nv_bfloat162(h0, h1);
    *(__nv_bfloat162*)(hi + off + 4) = __nv_bfloat162(h2, h3);
    *(__nv_bfloat162*)(lo + off) = __nv_bfloat162(l0, l1);
    *(__nv_bfloat162*)(lo + off + 4) = __nv_bfloat162(l2, l3);
}

__global__ void qsplit_all(const float* __restrict__ x,
                           const float* __restrict__ W1l, const float* __restrict__ W1r,
                           const float* __restrict__ W2l, const float* __restrict__ W2r,
                           uint8_t* __restrict__ xhi, uint8_t* __restrict__ xlo, int M) {
    int i = blockIdx.x * blockDim.x + threadIdx.x;
    int nx = M * 64;
    if (i < nx) {
        int m = i >> 6, kq4 = i & 63;
        store_p(xhi, xlo, ((size_t)(kq4 >> 3) * MPAD + m) * ROWB, kq4, ((const float4*)x)[i]);
        return;
    }
    int j = i - nx;
    if (j < 32768) {
        int row = j >> 6, kq4 = j & 63;
        const float* src = (row < 256) ? W1l : W1r;
        float4 v = ((const float4*)src)[(row & 255) * 64 + kq4];
        store_p(g_w1hi, g_w1lo, ((size_t)(kq4 >> 3) * 512 + row) * ROWB, kq4, v);
    } else if (j < 49152) {
        int b = j - 32768;
        int row = b >> 6, kq4 = b & 63;
        const float* src = (row < 128) ? W2l : W2r;
        int srow = (row < 128) ? row : row - 128;
        float4 v = ((const float4*)src)[srow * 64 + kq4];
        store_p(g_w2hi, g_w2lo, ((size_t)(kq4 >> 3) * 256 + row) * ROWB, kq4, v);
    }
}

// ---------------------------------------------------------------------------
__global__ void deg_kernel(const int* __restrict__ dst, float* __restrict__ deg, int E) {
    int i = blockIdx.x * blockDim.x + threadIdx.x;
    if (i < E) atomicAdd(&deg[dst[i]], 1.0f);
}
__global__ void scan_part(const float* __restrict__ deg, int* __restrict__ bsum, int N) {
    __shared__ int sm[256];
    int b = blockIdx.x, t = threadIdx.x, s = 0;
#pragma unroll
    for (int k = 0; k < 4; k++) {
        int i = b * SCAN_BLK + t * 4 + k;
        if (i < N) s += (int)deg[i];
    }
    sm[t] = s; __syncthreads();
    for (int o = 128; o > 0; o >>= 1) { if (t < o) sm[t] += sm[t + o]; __syncthreads(); }
    if (t == 0) bsum[b] = sm[0];
}
__global__ void scan_sums(const int* __restrict__ bsum, int* __restrict__ boff, int nb) {
    __shared__ int sm[128];
    int t = threadIdx.x;
    sm[t] = (t < nb) ? bsum[t] : 0; __syncthreads();
    for (int o = 1; o < 128; o <<= 1) {
        int v = (t >= o) ? sm[t - o] : 0; __syncthreads();
        sm[t] += v; __syncthreads();
    }
    if (t < nb) boff[t] = (t == 0) ? 0 : sm[t - 1];
}
__global__ void scan_write(const float* __restrict__ deg, const int* __restrict__ boff,
                           int* __restrict__ rowptr, int* __restrict__ cursor, int N) {
    __shared__ int sm[256];
    int b = blockIdx.x, t = threadIdx.x, d[4], s = 0;
#pragma unroll
    for (int k = 0; k < 4; k++) {
        int i = b * SCAN_BLK + t * 4 + k;
        d[k] = (i < N) ? (int)deg[i] : 0; s += d[k];
    }
    sm[t] = s; __syncthreads();
    for (int o = 1; o < 256; o <<= 1) {
        int v = (t >= o) ? sm[t - o] : 0; __syncthreads();
        sm[t] += v; __syncthreads();
    }
    int off = boff[b] + ((t == 0) ? 0 : sm[t - 1]);
#pragma unroll
    for (int k = 0; k < 4; k++) {
        int i = b * SCAN_BLK + t * 4 + k;
        if (i < N) { rowptr[i] = off; cursor[i] = off; }
        off += d[k];
    }
}
__global__ void fill_csr(const int* __restrict__ src, const int* __restrict__ dst,
                         int* __restrict__ cursor, int* __restrict__ csr, int E) {
    int i = blockIdx.x * blockDim.x + threadIdx.x;
    if (i >= E) return;
    csr[atomicAdd(&cursor[dst[i]], 1)] = src[i];
}

// ---------------------------------------------------------------------------
__device__ __forceinline__ float4 bf16x4_load(const __nv_bfloat16* p) {
    uint2 raw = *(const uint2*)p;
    __nv_bfloat162 a = *reinterpret_cast<__nv_bfloat162*>(&raw.x);
    __nv_bfloat162 b = *reinterpret_cast<__nv_bfloat162*>(&raw.y);
    float2 f0 = __bfloat1622float2(a), f1 = __bfloat1622float2(b);
    return make_float4(f0.x, f0.y, f1.x, f1.y);
}

// MLP-2 neighbor sum: prefetch next row while accumulating current.
template <int D>
__device__ __forceinline__ float4 nbr_sum(const __nv_bfloat16* __restrict__ y,
                                          const int* __restrict__ csr,
                                          int start, int cnt, int off, int lane) {
    float4 acc = make_float4(0.f, 0.f, 0.f, 0.f);
    for (int j0 = 0; j0 < cnt; j0 += 32) {
        int m = min(32, cnt - j0);
        int sid = (lane < m) ? csr[start + j0 + lane] : 0;
        int s0 = __shfl_sync(0xffffffff, sid, 0);
        float4 v = bf16x4_load(y + (size_t)s0 * D + off);
        for (int t = 1; t < m; t++) {
            int sN = __shfl_sync(0xffffffff, sid, t);
            float4 vn = bf16x4_load(y + (size_t)sN * D + off);
            acc.x += v.x; acc.y += v.y; acc.z += v.z; acc.w += v.w;
            v = vn;
        }
        acc.x += v.x; acc.y += v.y; acc.z += v.z; acc.w += v.w;
    }
    return acc;
}

__global__ void gather1(const __nv_bfloat16* __restrict__ y, const float* __restrict__ z,
                        const int* __restrict__ rowptr, const int* __restrict__ csr,
                        const float* __restrict__ deg,
                        uint8_t* __restrict__ hhi, uint8_t* __restrict__ hlo, int N) {
    int gw = (blockIdx.x * blockDim.x + threadIdx.x) >> 5;
    int lane = threadIdx.x & 31;
    int node = gw >> 1, c0 = (gw & 1) * 128;
    if (node >= N) return;
    float degf = deg[node];
    int cnt = (int)degf;
    float4 acc = make_float4(0.f, 0.f, 0.f, 0.f);
    if (cnt > 0) acc = nbr_sum<D1>(y, csr, rowptr[node], cnt, c0 + lane * 4, lane);
    float sc = 1.0f / fmaxf(degf, 1.0f);
    float4 zz = *(const float4*)(z + (size_t)node * D1 + c0 + lane * 4);
    float4 r = make_float4(fmaxf(acc.x * sc + zz.x, 0.f), fmaxf(acc.y * sc + zz.y, 0.f),
                           fmaxf(acc.z * sc + zz.z, 0.f), fmaxf(acc.w * sc + zz.w, 0.f));
    int k = c0 + lane * 4;
    store_p(hhi, hlo, ((size_t)(k >> 5) * MPAD + node) * ROWB, k >> 2, r);
}

__global__ void gather2(const __nv_bfloat16* __restrict__ y, const float* __restrict__ z,
                        const int* __restrict__ rowptr, const int* __restrict__ csr,
                        const float* __restrict__ deg, float* __restrict__ out, int N) {
    int node = (blockIdx.x * blockDim.x + threadIdx.x) >> 5;
    int lane = threadIdx.x & 31;
    if (node >= N) return;
    float degf = deg[node];
    int cnt = (int)degf;
    float4 acc = make_float4(0.f, 0.f, 0.f, 0.f);
    if (cnt > 0) acc = nbr_sum<D2>(y, csr, rowptr[node], cnt, lane * 4, lane);
    float sc = 1.0f / fmaxf(degf, 1.0f);
    float4 zz = *(const float4*)(z + (size_t)node * D2 + lane * 4);
    *(float4*)(out + (size_t)node * D2 + lane * 4) =
        make_float4(acc.x * sc + zz.x, acc.y * sc + zz.y, acc.z * sc + zz.z, acc.w * sc + zz.w);
}

// ---------------------------------------------------------------------------
extern "C" void kernel_launch(void* const* d_in, const int* in_sizes, int n_in,
                              void* d_out, int out_size) {
    const float* x   = (const float*)d_in[0];
    const int* eidx  = (const int*)d_in[1];
    const float* W1l = (const float*)d_in[2];
    const float* b1  = (const float*)d_in[3];
    const float* W1r = (const float*)d_in[4];
    const float* W2l = (const float*)d_in[5];
    const float* b2  = (const float*)d_in[6];
    const float* W2r = (const float*)d_in[7];
    float* out = (float*)d_out;

    const int N = in_sizes[0] / D1;
    const int E = in_sizes[1] / 2;
    const int* src = eidx;
    const int* dst = eidx + E;

    __nv_bfloat16 *y1, *y2;
    float *z1, *z2, *deg;
    uint8_t *xhi, *xlo, *hhi, *hlo, *w1hi, *w1lo, *w2hi, *w2lo;
    int *rowptr, *cursor, *csr, *bsum, *boff;
    cudaGetSymbolAddress((void**)&y1, g_y1);
    cudaGetSymbolAddress((void**)&z1, g_z1);
    cudaGetSymbolAddress((void**)&y2, g_y2);
    cudaGetSymbolAddress((void**)&z2, g_z2);
    cudaGetSymbolAddress((void**)&deg, g_deg);
    cudaGetSymbolAddress((void**)&xhi, g_xhi);
    cudaGetSymbolAddress((void**)&xlo, g_xlo);
    cudaGetSymbolAddress((void**)&hhi, g_hhi);
    cudaGetSymbolAddress((void**)&hlo, g_hlo);
    cudaGetSymbolAddress((void**)&w1hi, g_w1hi);
    cudaGetSymbolAddress((void**)&w1lo, g_w1lo);
    cudaGetSymbolAddress((void**)&w2hi, g_w2hi);
    cudaGetSymbolAddress((void**)&w2lo, g_w2lo);
    cudaGetSymbolAddress((void**)&rowptr, g_rowptr);
    cudaGetSymbolAddress((void**)&cursor, g_cursor);
    cudaGetSymbolAddress((void**)&csr, g_csr);
    cudaGetSymbolAddress((void**)&bsum, g_bsum);
    cudaGetSymbolAddress((void**)&boff, g_boff);

    cudaFuncSetAttribute(gemm3, cudaFuncAttributeMaxDynamicSharedMemorySize, GEMM_SMEM);

    const int mb = (N + 127) / 128;
    const int nb = (N + SCAN_BLK - 1) / SCAN_BLK;

    cudaStream_t s2;
    cudaStreamCreateWithFlags(&s2, cudaStreamNonBlocking);
    cudaEvent_t evFork, evJoin;
    cudaEventCreateWithFlags(&evFork, cudaEventDisableTiming);
    cudaEventCreateWithFlags(&evJoin, cudaEventDisableTiming);

    cudaEventRecord(evFork, 0);
    cudaStreamWaitEvent(s2, evFork, 0);

    // submission order engineered: slot 4 (non-memset) = gather1
    cudaMemsetAsync(deg, 0, (size_t)N * sizeof(float), s2);
    qsplit_all<<<(N * 64 + 49152 + 255) / 256, 256>>>(x, W1l, W1r, W2l, W2r, xhi, xlo, N); // 1
    gemm3<<<2 * mb, 512, GEMM_SMEM>>>(xhi, xlo, w1hi, w1lo, 512, 2, 256,
                                      y1, D1, z1, D1, b1, N);                              // 2
    deg_kernel<<<(E + 255) / 256, 256, 0, s2>>>(dst, deg, E);                              // 3
    cudaStreamWaitEvent(0, evJoin, 0);  // placeholder wait recorded below? (must record first)
    // NOTE: evJoin must be recorded before the wait is submitted — restructure:
    // (we submit side-chain kernels now, record evJoin, then gather1)
    scan_part<<<nb, 256, 0, s2>>>(deg, bsum, N);                                           // 5*
    scan_sums<<<1, 128, 0, s2>>>(bsum, boff, nb);                                          // 6*
    scan_write<<<nb, 256, 0, s2>>>(deg, boff, rowptr, cursor, N);                          // 7*
    fill_csr<<<(E + 255) / 256, 256, 0, s2>>>(src, dst, cursor, csr, E);                   // 8*
    cudaEventRecord(evJoin, s2);
    cudaStreamWaitEvent(0, evJoin, 0);
    gather1<<<(2 * N * 32 + 255) / 256, 256>>>(y1, z1, rowptr, csr, deg, hhi, hlo, N);
    gemm3<<<mb, 512, GEMM_SMEM>>>(hhi, hlo, w2hi, w2lo, 256, 1, 128,
                                  y2, D2, z2, D2, b2, N);
    gather2<<<(N * 32 + 255) / 256, 256>>>(y2, z2, rowptr, csr, deg, out, N);

    cudaEventDestroy(evFork);
    cudaEventDestroy(evJoin);
    cudaStreamDestroy(s2);
}

// round 16
// speedup vs baseline: 1.0817x; 1.0817x over previous
#include <cuda_runtime.h>
#include <cuda_bf16.h>
#include <cstdint>

#define D1 256
#define D2 128
#define K_DIM 256
#define ROWB 80
#define MPAD 100096

static const int MAX_N = 100000;
static const int MAX_E = 1600000;

__device__ __nv_bfloat16 g_y1[MAX_N * D1];
__device__ float g_z1[MAX_N * D1];
__device__ __nv_bfloat16 g_y2[MAX_N * D2];
__device__ float g_z2[MAX_N * D2];
__device__ float g_deg[MAX_N];
__device__ uint8_t g_xhi[8ull * MPAD * ROWB];
__device__ uint8_t g_xlo[8ull * MPAD * ROWB];
__device__ uint8_t g_hhi[8ull * MPAD * ROWB];
__device__ uint8_t g_hlo[8ull * MPAD * ROWB];
__device__ uint8_t g_w1hi[8 * 512 * ROWB];
__device__ uint8_t g_w1lo[8 * 512 * ROWB];
__device__ uint8_t g_w2hi[8 * 256 * ROWB];
__device__ uint8_t g_w2lo[8 * 256 * ROWB];
__device__ int g_rowptr[MAX_N];
__device__ int g_cursor[MAX_N];
__device__ int g_csr[MAX_E];
__device__ int g_bsum[128];
__device__ int g_boff[128];

#define SCAN_BLK 1024

__device__ __forceinline__ uint32_t smem_to_u32(const void* p) {
    uint32_t a;
    asm("{ .reg .u64 t; cvta.to.shared.u64 t, %1; cvt.u32.u64 %0, t; }" : "=r"(a) : "l"(p));
    return a;
}
__device__ __forceinline__ void mma_bf16(float* c, const uint32_t* a, const uint32_t* b) {
    asm volatile("mma.sync.aligned.m16n8k16.row.col.f32.bf16.bf16.f32 "
                 "{%0,%1,%2,%3}, {%4,%5,%6,%7}, {%8,%9}, {%0,%1,%2,%3};"
                 : "+f"(c[0]), "+f"(c[1]), "+f"(c[2]), "+f"(c[3])
                 : "r"(a[0]), "r"(a[1]), "r"(a[2]), "r"(a[3]), "r"(b[0]), "r"(b[1]));
}
#define LDSM_X4(r, addr) \
    asm volatile("ldmatrix.sync.aligned.m8n8.x4.shared.b16 {%0,%1,%2,%3}, [%4];" \
                 : "=r"((r)[0]), "=r"((r)[1]), "=r"((r)[2]), "=r"((r)[3]) : "r"(addr))
#define MBAR_INIT(a, c) \
    asm volatile("mbarrier.init.shared.b64 [%0], %1;" :: "r"((uint32_t)(a)), "r"((uint32_t)(c)) : "memory")
#define MBAR_TX(a, b) \
    asm volatile("mbarrier.arrive.expect_tx.shared.b64 _, [%0], %1;" :: "r"((uint32_t)(a)), "r"((uint32_t)(b)) : "memory")
#define MBAR_WAIT(a, ph) do { \
    uint32_t _m = (uint32_t)(a), _p = (uint32_t)(ph), _d; \
    asm volatile("{\n\t.reg .pred p;\n\t" \
        "mbarrier.try_wait.parity.acquire.cta.shared::cta.b64 p, [%1], %2;\n\t" \
        "selp.b32 %0, 1, 0, p;\n\t}" : "=r"(_d) : "r"(_m), "r"(_p) : "memory"); \
    if (!_d) { \
        asm volatile("{\n\t.reg .pred P1;\n\t" \
            "WL_%=:\n\t" \
            "mbarrier.try_wait.parity.acquire.cta.shared::cta.b64 P1, [%0], %1, 0x989680;\n\t" \
            "@P1 bra.uni WD_%=;\n\t bra.uni WL_%=;\n\t WD_%=:\n\t}" \
            :: "r"(_m), "r"(_p) : "memory"); \
    } \
} while (0)
__device__ __forceinline__ void tma_bulk(uint32_t dst, const void* src, uint32_t bytes, uint32_t mbar) {
    asm volatile("cp.async.bulk.shared::cluster.global.mbarrier::complete_tx::bytes [%0], [%1], %2, [%3];"
                 :: "r"(dst), "l"(src), "r"(bytes), "r"(mbar) : "memory");
}

// ---------------------------------------------------------------------------
#define AHI_O 0
#define ALO_O (128 * ROWB)
#define BHI_O (256 * ROWB)
#define BLO_O (512 * ROWB)
#define STG (768 * ROWB)
#define MB_O (3 * STG)
#define GEMM_SMEM (3 * STG + 64)

__global__ __launch_bounds__(512, 1)
void gemm3(const uint8_t* __restrict__ Ahi, const uint8_t* __restrict__ Alo,
           const uint8_t* __restrict__ Whi, const uint8_t* __restrict__ Wlo,
           int WR, int ncb, int NSPLIT,
           __nv_bfloat16* __restrict__ outY, int ldY,
           float* __restrict__ outZ, int ldZ, const float* __restrict__ biasZ, int M) {
    extern __shared__ char smem[];
    const uint32_t sb = smem_to_u32(smem);
    const uint32_t mb = sb + MB_O;
    const int tid = threadIdx.x, wid = tid >> 5, lane = tid & 31;
    const int wr = wid >> 2, wc = wid & 3;
    const int m0 = ((int)blockIdx.x / ncb) * 128;
    const int n0 = ((int)blockIdx.x % ncb) * 256;

    float acc[2][8][4];
#pragma unroll
    for (int i = 0; i < 2; i++)
#pragma unroll
        for (int j = 0; j < 8; j++)
#pragma unroll
            for (int k = 0; k < 4; k++) acc[i][j][k] = 0.0f;

    if (tid == 0) { MBAR_INIT(mb, 1); MBAR_INIT(mb + 8, 1); MBAR_INIT(mb + 16, 1); }
    __syncthreads();

    auto issue = [&](int c, int st) {
        uint32_t m = mb + st * 8;
        uint32_t s0 = sb + (uint32_t)st * STG;
        MBAR_TX(m, STG);
        tma_bulk(s0 + AHI_O, Ahi + ((size_t)c * MPAD + m0) * ROWB, 128 * ROWB, m);
        tma_bulk(s0 + ALO_O, Alo + ((size_t)c * MPAD + m0) * ROWB, 128 * ROWB, m);
        tma_bulk(s0 + BHI_O, Whi + ((size_t)c * WR + n0) * ROWB, 256 * ROWB, m);
        tma_bulk(s0 + BLO_O, Wlo + ((size_t)c * WR + n0) * ROWB, 256 * ROWB, m);
    };
    if (tid == 0) { issue(0, 0); issue(1, 1); }

    for (int c = 0; c < 8; c++) {
        MBAR_WAIT(mb + (c % 3) * 8, (c / 3) & 1);
        __syncthreads();
        if (tid == 0 && c + 2 < 8) issue(c + 2, (c + 2) % 3);

        const uint32_t s0 = sb + (uint32_t)(c % 3) * STG;
#pragma unroll
        for (int s = 0; s < 2; s++) {
            const uint32_t ao = s0 + (uint32_t)(wr * 32 + (lane & 15)) * ROWB + ((lane >> 4) << 4) + s * 32;
            const uint32_t bo = s0 + BHI_O + (uint32_t)(wc * 64 + (lane & 7) + ((lane >> 4) << 3)) * ROWB
                                + (((lane >> 3) & 1) << 4) + s * 32;
            uint32_t ahi[2][4], alo[2][4], bbf[4][4];
#pragma unroll
            for (int mi = 0; mi < 2; mi++) {
                LDSM_X4(ahi[mi], ao + mi * (16 * ROWB));
                LDSM_X4(alo[mi], ao + ALO_O + mi * (16 * ROWB));
            }
#pragma unroll
            for (int p = 0; p < 4; p++) LDSM_X4(bbf[p], bo + p * (16 * ROWB));
#pragma unroll
            for (int mi = 0; mi < 2; mi++)
#pragma unroll
                for (int p = 0; p < 4; p++) {
                    mma_bf16(acc[mi][2 * p], ahi[mi], &bbf[p][0]);
                    mma_bf16(acc[mi][2 * p + 1], ahi[mi], &bbf[p][2]);
                    mma_bf16(acc[mi][2 * p], alo[mi], &bbf[p][0]);
                    mma_bf16(acc[mi][2 * p + 1], alo[mi], &bbf[p][2]);
                }
#pragma unroll
            for (int p = 0; p < 4; p++) LDSM_X4(bbf[p], bo + (BLO_O - BHI_O) + p * (16 * ROWB));
#pragma unroll
            for (int mi = 0; mi < 2; mi++)
#pragma unroll
                for (int p = 0; p < 4; p++) {
                    mma_bf16(acc[mi][2 * p], ahi[mi], &bbf[p][0]);
                    mma_bf16(acc[mi][2 * p + 1], ahi[mi], &bbf[p][2]);
                }
        }
    }

    const int gc0 = n0 + wc * 64;
    if (gc0 >= NSPLIT) {
        const int cbase = gc0 - NSPLIT;
#pragma unroll
        for (int mi = 0; mi < 2; mi++) {
            int r0 = m0 + wr * 32 + mi * 16 + (lane >> 2), r1 = r0 + 8;
#pragma unroll
            for (int ni = 0; ni < 8; ni++) {
                int col = cbase + ni * 8 + 2 * (lane & 3);
                float bx = __ldg(biasZ + col), by = __ldg(biasZ + col + 1);
                if (r0 < M)
                    *(float2*)(outZ + (size_t)r0 * ldZ + col) = make_float2(acc[mi][ni][0] + bx, acc[mi][ni][1] + by);
                if (r1 < M)
                    *(float2*)(outZ + (size_t)r1 * ldZ + col) = make_float2(acc[mi][ni][2] + bx, acc[mi][ni][3] + by);
            }
        }
    } else {
#pragma unroll
        for (int mi = 0; mi < 2; mi++) {
            int r0 = m0 + wr * 32 + mi * 16 + (lane >> 2), r1 = r0 + 8;
#pragma unroll
            for (int ni = 0; ni < 8; ni++) {
                int col = gc0 + ni * 8 + 2 * (lane & 3);
                if (r0 < M)
                    *(__nv_bfloat162*)(outY + (size_t)r0 * ldY + col) =
                        __nv_bfloat162(__float2bfloat16(acc[mi][ni][0]), __float2bfloat16(acc[mi][ni][1]));
                if (r1 < M)
                    *(__nv_bfloat162*)(outY + (size_t)r1 * ldY + col) =
                        __nv_bfloat162(__float2bfloat16(acc[mi][ni][2]), __float2bfloat16(acc[mi][ni][3]));
            }
        }
    }
}

// ---------------------------------------------------------------------------
__device__ __forceinline__ void split1(float v, __nv_bfloat16& h, __nv_bfloat16& l) {
    h = __float2bfloat16(v);
    l = __float2bfloat16(v - __bfloat162float(h));
}
__device__ __forceinline__ void store_p(uint8_t* hi, uint8_t* lo, size_t rowbase, int kq4, float4 v) {
    __nv_bfloat16 h0, h1, h2, h3, l0, l1, l2, l3;
    split1(v.x, h0, l0); split1(v.y, h1, l1);
    split1(v.z, h2, l2); split1(v.w, h3, l3);
    size_t off = rowbase + (size_t)(kq4 & 7) * 8;
    *(__nv_bfloat162*)(hi + off) = __nv_bfloat162(h0, h1);
    *(__nv_bfloat162*)(hi + off + 4) = __nv_bfloat162(h2, h3);
    *(__nv_bfloat162*)(lo + off) = __nv_bfloat162(l0, l1);
    *(__nv_bfloat162*)(lo + off + 4) = __nv_bfloat162(l2, l3);
}

__global__ void qsplit_all(const float* __restrict__ x,
                           const float* __restrict__ W1l, const float* __restrict__ W1r,
                           const float* __restrict__ W2l, const float* __restrict__ W2r,
                           uint8_t* __restrict__ xhi, uint8_t* __restrict__ xlo, int M) {
    int i = blockIdx.x * blockDim.x + threadIdx.x;
    int nx = M * 64;
    if (i < nx) {
        int m = i >> 6, kq4 = i & 63;
        store_p(xhi, xlo, ((size_t)(kq4 >> 3) * MPAD + m) * ROWB, kq4, ((const float4*)x)[i]);
        return;
    }
    int j = i - nx;
    if (j < 32768) {
        int row = j >> 6, kq4 = j & 63;
        const float* src = (row < 256) ? W1l : W1r;
        float4 v = ((const float4*)src)[(row & 255) * 64 + kq4];
        store_p(g_w1hi, g_w1lo, ((size_t)(kq4 >> 3) * 512 + row) * ROWB, kq4, v);
    } else if (j < 49152) {
        int b = j - 32768;
        int row = b >> 6, kq4 = b & 63;
        const float* src = (row < 128) ? W2l : W2r;
        int srow = (row < 128) ? row : row - 128;
        float4 v = ((const float4*)src)[srow * 64 + kq4];
        store_p(g_w2hi, g_w2lo, ((size_t)(kq4 >> 3) * 256 + row) * ROWB, kq4, v);
    }
}

// ---------------------------------------------------------------------------
__global__ void deg_kernel(const int* __restrict__ dst, float* __restrict__ deg, int E) {
    int i = blockIdx.x * blockDim.x + threadIdx.x;
    if (i < E) atomicAdd(&deg[dst[i]], 1.0f);
}
__global__ void scan_part(const float* __restrict__ deg, int* __restrict__ bsum, int N) {
    __shared__ int sm[256];
    int b = blockIdx.x, t = threadIdx.x, s = 0;
#pragma unroll
    for (int k = 0; k < 4; k++) {
        int i = b * SCAN_BLK + t * 4 + k;
        if (i < N) s += (int)deg[i];
    }
    sm[t] = s; __syncthreads();
    for (int o = 128; o > 0; o >>= 1) { if (t < o) sm[t] += sm[t + o]; __syncthreads(); }
    if (t == 0) bsum[b] = sm[0];
}
__global__ void scan_sums(const int* __restrict__ bsum, int* __restrict__ boff, int nb) {
    __shared__ int sm[128];
    int t = threadIdx.x;
    sm[t] = (t < nb) ? bsum[t] : 0; __syncthreads();
    for (int o = 1; o < 128; o <<= 1) {
        int v = (t >= o) ? sm[t - o] : 0; __syncthreads();
        sm[t] += v; __syncthreads();
    }
    if (t < nb) boff[t] = (t == 0) ? 0 : sm[t - 1];
}
__global__ void scan_write(const float* __restrict__ deg, const int* __restrict__ boff,
                           int* __restrict__ rowptr, int* __restrict__ cursor, int N) {
    __shared__ int sm[256];
    int b = blockIdx.x, t = threadIdx.x, d[4], s = 0;
#pragma unroll
    for (int k = 0; k < 4; k++) {
        int i = b * SCAN_BLK + t * 4 + k;
        d[k] = (i < N) ? (int)deg[i] : 0; s += d[k];
    }
    sm[t] = s; __syncthreads();
    for (int o = 1; o < 256; o <<= 1) {
        int v = (t >= o) ? sm[t - o] : 0; __syncthreads();
        sm[t] += v; __syncthreads();
    }
    int off = boff[b] + ((t == 0) ? 0 : sm[t - 1]);
#pragma unroll
    for (int k = 0; k < 4; k++) {
        int i = b * SCAN_BLK + t * 4 + k;
        if (i < N) { rowptr[i] = off; cursor[i] = off; }
        off += d[k];
    }
}
__global__ void fill_csr(const int* __restrict__ src, const int* __restrict__ dst,
                         int* __restrict__ cursor, int* __restrict__ csr, int E) {
    int i = blockIdx.x * blockDim.x + threadIdx.x;
    if (i >= E) return;
    csr[atomicAdd(&cursor[dst[i]], 1)] = src[i];
}

// ---------------------------------------------------------------------------
__device__ __forceinline__ float4 bf16x4_unpack(uint2 raw) {
    __nv_bfloat162 a = *reinterpret_cast<__nv_bfloat162*>(&raw.x);
    __nv_bfloat162 b = *reinterpret_cast<__nv_bfloat162*>(&raw.y);
    float2 f0 = __bfloat1622float2(a), f1 = __bfloat1622float2(b);
    return make_float4(f0.x, f0.y, f1.x, f1.y);
}
__device__ __forceinline__ void acc4(float4& a, float4 v) {
    a.x += v.x; a.y += v.y; a.z += v.z; a.w += v.w;
}

// gather1: ONE warp per node, lane covers 8 columns (16B load per neighbor).
__global__ void gather1(const __nv_bfloat16* __restrict__ y, const float* __restrict__ z,
                        const int* __restrict__ rowptr, const int* __restrict__ csr,
                        const float* __restrict__ deg,
                        uint8_t* __restrict__ hhi, uint8_t* __restrict__ hlo, int N) {
    int node = (blockIdx.x * blockDim.x + threadIdx.x) >> 5;
    int lane = threadIdx.x & 31;
    if (node >= N) return;
    int start = rowptr[node];
    float degf = deg[node];
    int cnt = (int)degf;
    float4 accA = make_float4(0.f, 0.f, 0.f, 0.f);
    float4 accB = make_float4(0.f, 0.f, 0.f, 0.f);
    for (int j0 = 0; j0 < cnt; j0 += 32) {
        int m = min(32, cnt - j0);
        int sid = (lane < m) ? csr[start + j0 + lane] : 0;
        for (int t = 0; t < m; t++) {
            int sN = __shfl_sync(0xffffffff, sid, t);
            uint4 raw = *(const uint4*)(y + (size_t)sN * D1 + lane * 8);
            acc4(accA, bf16x4_unpack(make_uint2(raw.x, raw.y)));
            acc4(accB, bf16x4_unpack(make_uint2(raw.z, raw.w)));
        }
    }
    float sc = 1.0f / fmaxf(degf, 1.0f);
    int k = lane * 8;
    float4 zA = *(const float4*)(z + (size_t)node * D1 + k);
    float4 zB = *(const float4*)(z + (size_t)node * D1 + k + 4);
    float4 rA = make_float4(fmaxf(accA.x * sc + zA.x, 0.f), fmaxf(accA.y * sc + zA.y, 0.f),
                            fmaxf(accA.z * sc + zA.z, 0.f), fmaxf(accA.w * sc + zA.w, 0.f));
    float4 rB = make_float4(fmaxf(accB.x * sc + zB.x, 0.f), fmaxf(accB.y * sc + zB.y, 0.f),
                            fmaxf(accB.z * sc + zB.z, 0.f), fmaxf(accB.w * sc + zB.w, 0.f));
    store_p(hhi, hlo, ((size_t)(k >> 5) * MPAD + node) * ROWB, k >> 2, rA);
    store_p(hhi, hlo, ((size_t)((k + 4) >> 5) * MPAD + node) * ROWB, (k + 4) >> 2, rB);
}

__global__ void gather2(const __nv_bfloat16* __restrict__ y, const float* __restrict__ z,
                        const int* __restrict__ rowptr, const int* __restrict__ csr,
                        const float* __restrict__ deg, float* __restrict__ out, int N) {
    int node = (blockIdx.x * blockDim.x + threadIdx.x) >> 5;
    int lane = threadIdx.x & 31;
    if (node >= N) return;
    int start = rowptr[node];
    float degf = deg[node];
    int cnt = (int)degf;
    float4 acc = make_float4(0.f, 0.f, 0.f, 0.f);
    for (int j0 = 0; j0 < cnt; j0 += 32) {
        int m = min(32, cnt - j0);
        int sid = (lane < m) ? csr[start + j0 + lane] : 0;
        for (int t = 0; t < m; t++) {
            int sN = __shfl_sync(0xffffffff, sid, t);
            uint2 raw = *(const uint2*)(y + (size_t)sN * D2 + lane * 4);
            acc4(acc, bf16x4_unpack(raw));
        }
    }
    float sc = 1.0f / fmaxf(degf, 1.0f);
    float4 zz = *(const float4*)(z + (size_t)node * D2 + lane * 4);
    *(float4*)(out + (size_t)node * D2 + lane * 4) =
        make_float4(acc.x * sc + zz.x, acc.y * sc + zz.y, acc.z * sc + zz.z, acc.w * sc + zz.w);
}

// ---------------------------------------------------------------------------
extern "C" void kernel_launch(void* const* d_in, const int* in_sizes, int n_in,
                              void* d_out, int out_size) {
    const float* x   = (const float*)d_in[0];
    const int* eidx  = (const int*)d_in[1];
    const float* W1l = (const float*)d_in[2];
    const float* b1  = (const float*)d_in[3];
    const float* W1r = (const float*)d_in[4];
    const float* W2l = (const float*)d_in[5];
    const float* b2  = (const float*)d_in[6];
    const float* W2r = (const float*)d_in[7];
    float* out = (float*)d_out;

    const int N = in_sizes[0] / D1;
    const int E = in_sizes[1] / 2;
    const int* src = eidx;
    const int* dst = eidx + E;

    __nv_bfloat16 *y1, *y2;
    float *z1, *z2, *deg;
    uint8_t *xhi, *xlo, *hhi, *hlo, *w1hi, *w1lo, *w2hi, *w2lo;
    int *rowptr, *cursor, *csr, *bsum, *boff;
    cudaGetSymbolAddress((void**)&y1, g_y1);
    cudaGetSymbolAddress((void**)&z1, g_z1);
    cudaGetSymbolAddress((void**)&y2, g_y2);
    cudaGetSymbolAddress((void**)&z2, g_z2);
    cudaGetSymbolAddress((void**)&deg, g_deg);
    cudaGetSymbolAddress((void**)&xhi, g_xhi);
    cudaGetSymbolAddress((void**)&xlo, g_xlo);
    cudaGetSymbolAddress((void**)&hhi, g_hhi);
    cudaGetSymbolAddress((void**)&hlo, g_hlo);
    cudaGetSymbolAddress((void**)&w1hi, g_w1hi);
    cudaGetSymbolAddress((void**)&w1lo, g_w1lo);
    cudaGetSymbolAddress((void**)&w2hi, g_w2hi);
    cudaGetSymbolAddress((void**)&w2lo, g_w2lo);
    cudaGetSymbolAddress((void**)&rowptr, g_rowptr);
    cudaGetSymbolAddress((void**)&cursor, g_cursor);
    cudaGetSymbolAddress((void**)&csr, g_csr);
    cudaGetSymbolAddress((void**)&bsum, g_bsum);
    cudaGetSymbolAddress((void**)&boff, g_boff);

    cudaFuncSetAttribute(gemm3, cudaFuncAttributeMaxDynamicSharedMemorySize, GEMM_SMEM);

    const int mb = (N + 127) / 128;
    const int nb = (N + SCAN_BLK - 1) / SCAN_BLK;

    cudaStream_t s2;
    cudaStreamCreateWithFlags(&s2, cudaStreamNonBlocking);
    cudaEvent_t evFork, evJoin;
    cudaEventCreateWithFlags(&evFork, cudaEventDisableTiming);
    cudaEventCreateWithFlags(&evJoin, cudaEventDisableTiming);

    cudaEventRecord(evFork, 0);
    cudaStreamWaitEvent(s2, evFork, 0);

    // side stream: degree + CSR build (hidden under splits + gemm1)
    cudaMemsetAsync(deg, 0, (size_t)N * sizeof(float), s2);
    deg_kernel<<<(E + 255) / 256, 256, 0, s2>>>(dst, deg, E);
    scan_part<<<nb, 256, 0, s2>>>(deg, bsum, N);
    scan_sums<<<1, 128, 0, s2>>>(bsum, boff, nb);
    scan_write<<<nb, 256, 0, s2>>>(deg, boff, rowptr, cursor, N);
    fill_csr<<<(E + 255) / 256, 256, 0, s2>>>(src, dst, cursor, csr, E);
    cudaEventRecord(evJoin, s2);

    // main chain
    qsplit_all<<<(N * 64 + 49152 + 255) / 256, 256>>>(x, W1l, W1r, W2l, W2r, xhi, xlo, N);
    gemm3<<<2 * mb, 512, GEMM_SMEM>>>(xhi, xlo, w1hi, w1lo, 512, 2, 256,
                                      y1, D1, z1, D1, b1, N);
    cudaStreamWaitEvent(0, evJoin, 0);
    gather1<<<(N * 32 + 255) / 256, 256>>>(y1, z1, rowptr, csr, deg, hhi, hlo, N);
    gemm3<<<mb, 512, GEMM_SMEM>>>(hhi, hlo, w2hi, w2lo, 256, 1, 128,
                                  y2, D2, z2, D2, b2, N);
    gather2<<<(N * 32 + 255) / 256, 256>>>(y2, z2, rowptr, csr, deg, out, N);

    cudaEventDestroy(evFork);
    cudaEventDestroy(evJoin);
    cudaStreamDestroy(s2);
}